// round 2
// baseline (speedup 1.0000x reference)
#include <cuda_runtime.h>

// Tropical (max-plus) Gram matrix: H[i,j] = max_k (|W[i,k]| + |W[j,k]|)
// W: 2048 x 10000 fp32 row-major, H: 2048 x 2048 fp32.
//
// R2 changes vs R1:
//  - k-pair packed smem for BOTH operands: smem[kp][2*row+{0,1}] = |w[row][2kp+{0,1}]|.
//    Inner op: add.rn.f32x2(a_pair, b_pair) then __vimax3_s32(acc, lo, hi)
//    -> 2 updates per add, no A duplication. Smem bytes: 1.0 B/update (was 1.5).
//  - K split across blockIdx.y (2 halves) -> 272 CTAs = 2 CTAs/SM, combining
//    with atomicMax on int bits (all values >= 0, exact). H zero-initialized
//    by cudaMemsetAsync in kernel_launch.

constexpr int K_DIM  = 10000;
constexpr int N_DIM  = 2048;
constexpr int KSPLIT = 2;
constexpr int KHALF  = K_DIM / KSPLIT;    // 5000
constexpr int KT     = 8;                 // k per smem tile
constexpr int KP     = KT / 2;            // 4 k-pairs
constexpr int NKT    = KHALF / KT;        // 625
constexpr int TILE   = 128;
constexpr int NTILES = N_DIM / TILE;      // 16
constexpr int NPAIRS = NTILES * (NTILES + 1) / 2;  // 136
constexpr int ROWW   = 2 * TILE + 8;      // 264 floats (16B-aligned stride)

__device__ __forceinline__ unsigned long long add_f32x2(unsigned long long a,
                                                        unsigned long long b) {
    unsigned long long r;
    asm("add.rn.f32x2 %0, %1, %2;" : "=l"(r) : "l"(a), "l"(b));
    return r;
}
__device__ __forceinline__ int lo32(unsigned long long v) { return (int)(unsigned int)v; }
__device__ __forceinline__ int hi32(unsigned long long v) { return (int)(unsigned int)(v >> 32); }

__global__ void __launch_bounds__(256, 2)
tropical_gram_kernel(const float* __restrict__ W, float* __restrict__ H)
{
    __shared__ __align__(16) float As[2][KP][ROWW];
    __shared__ __align__(16) float Bs[2][KP][ROWW];

    // blockIdx.x -> upper-triangular tile pair (ti <= tj); blockIdx.y -> K half
    int rem = (int)blockIdx.x;
    int ti = 0;
    while (rem >= NTILES - ti) { rem -= NTILES - ti; ++ti; }
    const int tj = ti + rem;
    const int kbase0 = (int)blockIdx.y * KHALF;

    const int tid  = (int)threadIdx.x;
    const int tx   = tid & 15;        // j micro-tile (8 cols)
    const int ty   = tid >> 4;        // i micro-tile (8 rows)
    const int lrow = tid >> 1;        // 0..127 loader row
    const int lc4  = (tid & 1) << 2;  // 0 or 4 (float4 slot in k-tile)
    const int lkp  = lc4 >> 1;        // 0 or 2 (k-pair base in smem)

    const float* Aptr = W + (size_t)(ti * TILE + lrow) * K_DIM + kbase0 + lc4;
    const float* Bptr = W + (size_t)(tj * TILE + lrow) * K_DIM + kbase0 + lc4;

    int acc[8][8];
#pragma unroll
    for (int i = 0; i < 8; ++i)
#pragma unroll
        for (int j = 0; j < 8; ++j) acc[i][j] = 0;

    // ---- prefetch + store k-tile 0 ----
    float4 av = *(const float4*)Aptr;
    float4 bv = *(const float4*)Bptr;
    *(float2*)&As[0][lkp + 0][2 * lrow] = make_float2(fabsf(av.x), fabsf(av.y));
    *(float2*)&As[0][lkp + 1][2 * lrow] = make_float2(fabsf(av.z), fabsf(av.w));
    *(float2*)&Bs[0][lkp + 0][2 * lrow] = make_float2(fabsf(bv.x), fabsf(bv.y));
    *(float2*)&Bs[0][lkp + 1][2 * lrow] = make_float2(fabsf(bv.z), fabsf(bv.w));
    __syncthreads();

    int buf = 0;
#pragma unroll 1
    for (int t = 0; t < NKT; ++t) {
        if (t + 1 < NKT) {
            av = *(const float4*)(Aptr + (size_t)(t + 1) * KT);
            bv = *(const float4*)(Bptr + (size_t)(t + 1) * KT);
        }

#pragma unroll
        for (int kp = 0; kp < KP; ++kp) {
            const ulonglong2* ap = (const ulonglong2*)&As[buf][kp][ty * 16];
            const ulonglong2* bp = (const ulonglong2*)&Bs[buf][kp][tx * 16];
            ulonglong2 a0 = ap[0], a1 = ap[1], a2 = ap[2], a3 = ap[3];
            ulonglong2 b0 = bp[0], b1 = bp[1], b2 = bp[2], b3 = bp[3];
            unsigned long long a[8] = {a0.x, a0.y, a1.x, a1.y, a2.x, a2.y, a3.x, a3.y};
            unsigned long long b[8] = {b0.x, b0.y, b1.x, b1.y, b2.x, b2.y, b3.x, b3.y};

#pragma unroll
            for (int i = 0; i < 8; ++i) {
#pragma unroll
                for (int j = 0; j < 8; ++j) {
                    unsigned long long s = add_f32x2(a[i], b[j]);
                    acc[i][j] = __vimax3_s32(acc[i][j], lo32(s), hi32(s));
                }
            }
        }

        if (t + 1 < NKT) {
            const int nb = buf ^ 1;
            *(float2*)&As[nb][lkp + 0][2 * lrow] = make_float2(fabsf(av.x), fabsf(av.y));
            *(float2*)&As[nb][lkp + 1][2 * lrow] = make_float2(fabsf(av.z), fabsf(av.w));
            *(float2*)&Bs[nb][lkp + 0][2 * lrow] = make_float2(fabsf(bv.x), fabsf(bv.y));
            *(float2*)&Bs[nb][lkp + 1][2 * lrow] = make_float2(fabsf(bv.z), fabsf(bv.w));
            __syncthreads();
            buf = nb;
        }
    }

    // ---- epilogue: atomic-max combine (2 K-halves write the same tile) ----
    const int gi = ti * TILE + ty * 8;
    const int gj = tj * TILE + tx * 8;
    int* Hi = (int*)H;
#pragma unroll
    for (int i = 0; i < 8; ++i)
#pragma unroll
        for (int j = 0; j < 8; ++j)
            atomicMax(&Hi[(size_t)(gi + i) * N_DIM + gj + j], acc[i][j]);
    if (ti != tj) {
#pragma unroll
        for (int j = 0; j < 8; ++j)
#pragma unroll
            for (int i = 0; i < 8; ++i)
                atomicMax(&Hi[(size_t)(gj + j) * N_DIM + gi + i], acc[i][j]);
    }
}

extern "C" void kernel_launch(void* const* d_in, const int* in_sizes, int n_in,
                              void* d_out, int out_size) {
    const float* W = (const float*)d_in[0];
    float* H = (float*)d_out;
    cudaMemsetAsync(d_out, 0, (size_t)out_size * sizeof(float));
    dim3 grid(NPAIRS, KSPLIT);
    tropical_gram_kernel<<<grid, 256>>>(W, H);
}

// round 3
// speedup vs baseline: 1.2706x; 1.2706x over previous
#include <cuda_runtime.h>

// Tropical (max-plus) Gram matrix: H[i,j] = max_k (|W[i,k]| + |W[j,k]|)
// W: 2048 x 10000 fp32 row-major, H: 2048 x 2048 fp32.
//
// R3 changes vs R2:
//  - XOR-swizzled k-pair smem layout: pair of row r in kp-row stored at
//    position p(r) = l*32 + ((r>>3)^l)*2 + (r&1), l=(r>>1)&3.
//    Compute-side LDS.128 for B becomes 16B-stride across lanes -> conflict-free.
//    A-side loads remain warp broadcasts. kp-row stride padded to 132 pairs
//    (1056B) so paired loader lanes (kp vs kp+2) are 16 banks apart -> stores
//    conflict-free too.
//  - Math unchanged: add.rn.f32x2 + __vimax3_s32 (2 updates / add / max).
//  - K split in 2 (272 CTAs = 2/SM), exact atomicMax(int) combine; all values
//    >= 0 so fp32 order == s32 bit order. H zeroed via cudaMemsetAsync.

constexpr int K_DIM  = 10000;
constexpr int N_DIM  = 2048;
constexpr int KSPLIT = 2;
constexpr int KHALF  = K_DIM / KSPLIT;    // 5000
constexpr int KT     = 8;                 // k per smem tile
constexpr int KP     = KT / 2;            // 4 k-pair rows
constexpr int NKT    = KHALF / KT;        // 625
constexpr int TILE   = 128;
constexpr int NTILES = N_DIM / TILE;      // 16
constexpr int NPAIRS = NTILES * (NTILES + 1) / 2;  // 136
constexpr int ROWP   = 132;               // pairs per kp-row (128 + 4 pad)

__device__ __forceinline__ unsigned long long add_f32x2(unsigned long long a,
                                                        unsigned long long b) {
    unsigned long long r;
    asm("add.rn.f32x2 %0, %1, %2;" : "=l"(r) : "l"(a), "l"(b));
    return r;
}
__device__ __forceinline__ int lo32(unsigned long long v) { return (int)(unsigned int)v; }
__device__ __forceinline__ int hi32(unsigned long long v) { return (int)(unsigned int)(v >> 32); }

// swizzled position of row r within a kp-row (in 8-byte pair units)
__device__ __forceinline__ int perm_pos(int r) {
    int l = (r >> 1) & 3;
    return l * 32 + (((r >> 3) ^ l) << 1) + (r & 1);
}

__global__ void __launch_bounds__(256, 2)
tropical_gram_kernel(const float* __restrict__ W, float* __restrict__ H)
{
    __shared__ __align__(16) unsigned long long As[2][KP][ROWP];
    __shared__ __align__(16) unsigned long long Bs[2][KP][ROWP];

    // blockIdx.x -> upper-triangular tile pair (ti <= tj); blockIdx.y -> K half
    int rem = (int)blockIdx.x;
    int ti = 0;
    while (rem >= NTILES - ti) { rem -= NTILES - ti; ++ti; }
    const int tj = ti + rem;
    const int kbase0 = (int)blockIdx.y * KHALF;

    const int tid  = (int)threadIdx.x;
    const int tx   = tid & 15;        // j micro-tile (8 cols)
    const int ty   = tid >> 4;        // i micro-tile (8 rows)
    const int lrow = tid >> 1;        // 0..127 loader row
    const int lc4  = (tid & 1) << 2;  // 0 or 4 (float4 slot in k-tile)
    const int lkp  = lc4 >> 1;        // kp row base: 0 or 2

    // compute-side swizzled offsets (pair units), constant per thread
    int aofs[4], bofs[4];
#pragma unroll
    for (int l = 0; l < 4; ++l) {
        aofs[l] = l * 32 + ((ty ^ l) << 1);
        bofs[l] = l * 32 + ((tx ^ l) << 1);
    }
    const int sp = perm_pos(lrow);    // store position for loader row

    const float* Aptr = W + (size_t)(ti * TILE + lrow) * K_DIM + kbase0 + lc4;
    const float* Bptr = W + (size_t)(tj * TILE + lrow) * K_DIM + kbase0 + lc4;

    int acc[8][8];
#pragma unroll
    for (int i = 0; i < 8; ++i)
#pragma unroll
        for (int j = 0; j < 8; ++j) acc[i][j] = 0;

    // ---- prefetch + store k-tile 0 ----
    float4 av = *(const float4*)Aptr;
    float4 bv = *(const float4*)Bptr;
    *(float2*)&As[0][lkp + 0][sp] = make_float2(fabsf(av.x), fabsf(av.y));
    *(float2*)&As[0][lkp + 1][sp] = make_float2(fabsf(av.z), fabsf(av.w));
    *(float2*)&Bs[0][lkp + 0][sp] = make_float2(fabsf(bv.x), fabsf(bv.y));
    *(float2*)&Bs[0][lkp + 1][sp] = make_float2(fabsf(bv.z), fabsf(bv.w));
    __syncthreads();

    int buf = 0;
#pragma unroll 1
    for (int t = 0; t < NKT; ++t) {
        if (t + 1 < NKT) {
            av = *(const float4*)(Aptr + (size_t)(t + 1) * KT);
            bv = *(const float4*)(Bptr + (size_t)(t + 1) * KT);
        }

#pragma unroll
        for (int kp = 0; kp < KP; ++kp) {
            unsigned long long a[8], b[8];
#pragma unroll
            for (int l = 0; l < 4; ++l) {
                ulonglong2 a2 = *(const ulonglong2*)&As[buf][kp][aofs[l]];
                ulonglong2 b2 = *(const ulonglong2*)&Bs[buf][kp][bofs[l]];
                a[2 * l] = a2.x; a[2 * l + 1] = a2.y;
                b[2 * l] = b2.x; b[2 * l + 1] = b2.y;
            }
#pragma unroll
            for (int i = 0; i < 8; ++i) {
#pragma unroll
                for (int j = 0; j < 8; ++j) {
                    unsigned long long s = add_f32x2(a[i], b[j]);
                    acc[i][j] = __vimax3_s32(acc[i][j], lo32(s), hi32(s));
                }
            }
        }

        if (t + 1 < NKT) {
            const int nb = buf ^ 1;
            *(float2*)&As[nb][lkp + 0][sp] = make_float2(fabsf(av.x), fabsf(av.y));
            *(float2*)&As[nb][lkp + 1][sp] = make_float2(fabsf(av.z), fabsf(av.w));
            *(float2*)&Bs[nb][lkp + 0][sp] = make_float2(fabsf(bv.x), fabsf(bv.y));
            *(float2*)&Bs[nb][lkp + 1][sp] = make_float2(fabsf(bv.z), fabsf(bv.w));
            __syncthreads();
            buf = nb;
        }
    }

    // ---- epilogue: atomic-max combine (2 K-halves write the same tile) ----
    const int gi = ti * TILE + ty * 8;
    const int gj = tj * TILE + tx * 8;
    int* Hi = (int*)H;
#pragma unroll
    for (int i = 0; i < 8; ++i)
#pragma unroll
        for (int j = 0; j < 8; ++j)
            atomicMax(&Hi[(size_t)(gi + i) * N_DIM + gj + j], acc[i][j]);
    if (ti != tj) {
#pragma unroll
        for (int j = 0; j < 8; ++j)
#pragma unroll
            for (int i = 0; i < 8; ++i)
                atomicMax(&Hi[(size_t)(gj + j) * N_DIM + gi + i], acc[i][j]);
    }
}

extern "C" void kernel_launch(void* const* d_in, const int* in_sizes, int n_in,
                              void* d_out, int out_size) {
    const float* W = (const float*)d_in[0];
    float* H = (float*)d_out;
    cudaMemsetAsync(d_out, 0, (size_t)out_size * sizeof(float));
    dim3 grid(NPAIRS, KSPLIT);
    tropical_gram_kernel<<<grid, 256>>>(W, H);
}

// round 5
// speedup vs baseline: 6.5565x; 5.1603x over previous
#include <cuda_runtime.h>
#include <cuda_bf16.h>
#include <mma.h>
#include <cstdint>

using namespace nvcuda;

// Tropical (max-plus) Gram matrix via log-sum-exp GEMM on HMMA (wmma bf16).
// H[i,j] = max_k(|W_ik|+|W_jk|)
//        = m_i + m_j + log( sum_k e^{L(|W_ik|-m_i)} e^{L(|W_jk|-m_j)} ) / L
// L=2600: bias log(1+T)/L ~ 1.3e-4 typ.; factor underflow P ~ 1e-10/pair.
// Pipeline: rowmax -> E=bf16(exp(L(|W|-m_i))) (K padded to 10240 with zeros)
// -> 136 upper-tri 128x128-tile CTAs: cp.async double-buffered smem, wmma
// bf16 16x16x16 MMA (fp32 accum), epilogue log + mirror write.

constexpr int N_DIM = 2048;
constexpr int K_DIM = 10000;
constexpr int K_PAD = 10240;
constexpr float LMB = 2600.0f;
constexpr int NTILES = 16;
constexpr int NPAIRS = 136;          // upper-triangular tile pairs
constexpr int KTS  = 32;             // k per pipeline stage
constexpr int NSTG = K_PAD / KTS;    // 320
constexpr int ESTR = 40;             // smem row stride (bf16 elems), 80B
constexpr int STAGE_BYTES = 128 * ESTR * 2;   // 10240 per operand tile
constexpr int LDC = 132;             // epilogue scratch stride (floats)
constexpr int SMEM_DYN = 128 * LDC * 4 + 1024;  // max(pipeline 40960, scratch 67584)+pad

__device__ __nv_bfloat16 g_E[(size_t)N_DIM * K_PAD];
__device__ float g_m[N_DIM];

__device__ __forceinline__ uint32_t smem_u32(const void* p) {
    uint32_t a;
    asm("{ .reg .u64 t; cvta.to.shared.u64 t, %1; cvt.u32.u64 %0, t; }" : "=r"(a) : "l"(p));
    return a;
}
__device__ __forceinline__ void cp16(uint32_t dst, const void* src) {
    asm volatile("cp.async.cg.shared.global [%0], [%1], 16;" :: "r"(dst), "l"(src) : "memory");
}
__device__ __forceinline__ void cp_commit() {
    asm volatile("cp.async.commit_group;" ::: "memory");
}
__device__ __forceinline__ void cp_wait1() {
    asm volatile("cp.async.wait_group 1;" ::: "memory");
}
__device__ __forceinline__ void cp_wait0() {
    asm volatile("cp.async.wait_group 0;" ::: "memory");
}

// ---------------- kernel 1: per-row max of |W| ----------------
__global__ void rowmax_kernel(const float* __restrict__ W) {
    const int i = blockIdx.x;
    const int t = threadIdx.x;
    const float4* row = (const float4*)(W + (size_t)i * K_DIM);
    float m = 0.0f;
    for (int c = t; c < K_DIM / 4; c += 256) {
        float4 v = row[c];
        m = fmaxf(m, fmaxf(fmaxf(fabsf(v.x), fabsf(v.y)), fmaxf(fabsf(v.z), fabsf(v.w))));
    }
#pragma unroll
    for (int o = 16; o; o >>= 1) m = fmaxf(m, __shfl_xor_sync(~0u, m, o));
    __shared__ float red[8];
    if ((t & 31) == 0) red[t >> 5] = m;
    __syncthreads();
    if (t < 8) {
        float v = red[t];
#pragma unroll
        for (int o = 4; o; o >>= 1) v = fmaxf(v, __shfl_xor_sync(0xffu, v, o));
        if (t == 0) g_m[i] = v;
    }
}

// ---------------- kernel 2: E = bf16(exp(L*(|W|-m_i))), zero-padded ----------------
__global__ void expprep_kernel(const float* __restrict__ W) {
    const int i = blockIdx.x;
    const int base = (int)blockIdx.y * 2048 + (int)threadIdx.x * 8;
    const float m = g_m[i];
    __nv_bfloat16 out[8];
    if (base + 8 <= K_DIM) {
        const float4* p = (const float4*)(W + (size_t)i * K_DIM + base);
        float4 v0 = p[0], v1 = p[1];
        float vv[8] = {v0.x, v0.y, v0.z, v0.w, v1.x, v1.y, v1.z, v1.w};
#pragma unroll
        for (int q = 0; q < 8; ++q)
            out[q] = __float2bfloat16(__expf((fabsf(vv[q]) - m) * LMB));
    } else {
#pragma unroll
        for (int q = 0; q < 8; ++q) out[q] = __float2bfloat16(0.0f);
    }
    *(uint4*)(&g_E[(size_t)i * K_PAD + base]) = *(const uint4*)out;
}

// ---------------- kernel 3: wmma bf16 GEMM + log epilogue ----------------
__global__ void __launch_bounds__(256, 1)
lse_gemm_kernel(float* __restrict__ H)
{
    extern __shared__ char smem[];
    const uint32_t sb = smem_u32(smem);
    const int tid = (int)threadIdx.x;
    const int wid = tid >> 5;

    int rem = (int)blockIdx.x;
    int ti = 0;
    while (rem >= NTILES - ti) { rem -= NTILES - ti; ++ti; }
    const int tj = ti + rem;
    const int gi = ti * 128, gj = tj * 128;

    __shared__ float mjs[128];

    // warp tile: 4x2 warp grid, each warp 32(m) x 64(n)
    const int m0 = (wid & 3) * 32;
    const int n0 = (wid >> 2) * 64;

    wmma::fragment<wmma::accumulator, 16, 16, 16, float> acc[2][4];
#pragma unroll
    for (int a = 0; a < 2; ++a)
#pragma unroll
        for (int b = 0; b < 4; ++b) wmma::fill_fragment(acc[a][b], 0.0f);

    // ---- stage prefetch (4 x 16B chunks per thread: 512 A + 512 B chunks) ----
    auto prefetch = [&](int s) {
        const int buf = s & 1;
        const uint32_t abase = sb + buf * 2 * STAGE_BYTES;
        const uint32_t bbase = abase + STAGE_BYTES;
#pragma unroll
        for (int q = 0; q < 4; ++q) {
            int c = tid + 256 * q;            // 0..1023
            int isB = c >> 9;
            int cc = c & 511;
            int row = cc >> 2, sub = cc & 3;
            uint32_t dst = (isB ? bbase : abase) + (uint32_t)(row * (ESTR * 2) + sub * 16);
            const __nv_bfloat16* src =
                g_E + (size_t)((isB ? gj : gi) + row) * K_PAD + (size_t)s * KTS + sub * 8;
            cp16(dst, src);
        }
        cp_commit();
    };

    prefetch(0);

#pragma unroll 1
    for (int s = 0; s < NSTG; ++s) {
        if (s + 1 < NSTG) { prefetch(s + 1); cp_wait1(); }
        else              { cp_wait0(); }
        __syncthreads();

        const int buf = s & 1;
        const __nv_bfloat16* A = (const __nv_bfloat16*)(smem + buf * 2 * STAGE_BYTES);
        const __nv_bfloat16* B = (const __nv_bfloat16*)(smem + buf * 2 * STAGE_BYTES + STAGE_BYTES);
#pragma unroll
        for (int kk = 0; kk < KTS; kk += 16) {
            wmma::fragment<wmma::matrix_a, 16, 16, 16, __nv_bfloat16, wmma::row_major> af[2];
            wmma::fragment<wmma::matrix_b, 16, 16, 16, __nv_bfloat16, wmma::col_major> bfr[4];
#pragma unroll
            for (int a = 0; a < 2; ++a)
                wmma::load_matrix_sync(af[a], A + (m0 + a * 16) * ESTR + kk, ESTR);
#pragma unroll
            for (int b = 0; b < 4; ++b)
                wmma::load_matrix_sync(bfr[b], B + (n0 + b * 16) * ESTR + kk, ESTR);
#pragma unroll
            for (int a = 0; a < 2; ++a)
#pragma unroll
                for (int b = 0; b < 4; ++b)
                    wmma::mma_sync(acc[a][b], af[a], bfr[b], acc[a][b]);
        }
        __syncthreads();   // before next prefetch overwrites buf (s&1)
    }

    // ---- epilogue: dump accumulators to smem scratch, apply m_i+m_j+log/L ----
    float* scratch = (float*)smem;
#pragma unroll
    for (int a = 0; a < 2; ++a)
#pragma unroll
        for (int b = 0; b < 4; ++b)
            wmma::store_matrix_sync(scratch + (size_t)(m0 + a * 16) * LDC + (n0 + b * 16),
                                    acc[a][b], LDC, wmma::mem_row_major);
    if (tid < 128) mjs[tid] = g_m[gj + tid];
    __syncthreads();

    const int r = tid >> 1, half = tid & 1;
    const float mi_v = g_m[gi + r];
    const float invL = 1.0f / LMB;
    const float* srow = scratch + (size_t)r * LDC + half * 64;
    const int cbase = half * 64;

#pragma unroll 1
    for (int c8 = 0; c8 < 64; c8 += 8) {
        float vals[8];
#pragma unroll
        for (int q = 0; q < 8; ++q)
            vals[q] = mi_v + mjs[cbase + c8 + q] + logf(srow[c8 + q]) * invL;
        float4 v0 = make_float4(vals[0], vals[1], vals[2], vals[3]);
        float4 v1 = make_float4(vals[4], vals[5], vals[6], vals[7]);
        *(float4*)&H[(size_t)(gi + r) * N_DIM + gj + cbase + c8]     = v0;
        *(float4*)&H[(size_t)(gi + r) * N_DIM + gj + cbase + c8 + 4] = v1;
        if (ti != tj) {
#pragma unroll
            for (int q = 0; q < 8; ++q)
                H[(size_t)(gj + cbase + c8 + q) * N_DIM + gi + r] = vals[q];
        }
    }
}

// ---------------- launcher ----------------
extern "C" void kernel_launch(void* const* d_in, const int* in_sizes, int n_in,
                              void* d_out, int out_size) {
    const float* W = (const float*)d_in[0];
    float* H = (float*)d_out;

    cudaFuncSetAttribute(lse_gemm_kernel, cudaFuncAttributeMaxDynamicSharedMemorySize, SMEM_DYN);

    rowmax_kernel<<<N_DIM, 256>>>(W);
    dim3 eg(N_DIM, K_PAD / 2048);
    expprep_kernel<<<eg, 256>>>(W);
    lse_gemm_kernel<<<NPAIRS, 256, SMEM_DYN>>>(H);
}

// round 6
// speedup vs baseline: 6.7518x; 1.0298x over previous
#include <cuda_runtime.h>
#include <cuda_bf16.h>
#include <mma.h>
#include <cstdint>

using namespace nvcuda;

// Tropical (max-plus) Gram matrix via log-sum-exp GEMM on HMMA (wmma bf16).
// H[i,j] = m_i + m_j + log( sum_k e^{L(|W_ik|-m_i)} e^{L(|W_jk|-m_j)} ) / L
// R6 vs R5: fused rowmax+exp prep (one DRAM pass of W); GEMM uses a 4-deep
// cp.async pipeline (KTS=32, wait_group 2, single sync per stage); __logf.

constexpr int N_DIM = 2048;
constexpr int K_DIM = 10000;
constexpr int K_PAD = 10240;
constexpr float LMB = 2600.0f;
constexpr int NTILES = 16;
constexpr int NPAIRS = 136;
constexpr int KTS  = 32;                       // k per pipeline stage
constexpr int NSTG = K_PAD / KTS;              // 320
constexpr int ESTR = 40;                       // smem row stride (bf16), 80B
constexpr int STAGE_BYTES = 128 * ESTR * 2;    // 10240 per operand
constexpr int NBUF = 4;
constexpr int PIPE_BYTES = NBUF * 2 * STAGE_BYTES;   // 81920
constexpr int LDC = 132;                       // epilogue scratch stride
constexpr int SMEM_DYN = PIPE_BYTES;           // > scratch (67584)

__device__ __nv_bfloat16 g_E[(size_t)N_DIM * K_PAD];
__device__ float g_m[N_DIM];

__device__ __forceinline__ uint32_t smem_u32(const void* p) {
    uint32_t a;
    asm("{ .reg .u64 t; cvta.to.shared.u64 t, %1; cvt.u32.u64 %0, t; }" : "=r"(a) : "l"(p));
    return a;
}
__device__ __forceinline__ void cp16(uint32_t dst, const void* src) {
    asm volatile("cp.async.cg.shared.global [%0], [%1], 16;" :: "r"(dst), "l"(src) : "memory");
}
__device__ __forceinline__ void cp_commit() {
    asm volatile("cp.async.commit_group;" ::: "memory");
}
template <int N>
__device__ __forceinline__ void cp_wait() {
    asm volatile("cp.async.wait_group %0;" :: "n"(N) : "memory");
}

// ---------------- kernel 1: fused rowmax + E = bf16(exp(L*(|W|-m))) ----------------
__global__ void prep_kernel(const float* __restrict__ W) {
    const int i = blockIdx.x;
    const int t = threadIdx.x;
    const float4* row4 = (const float4*)(W + (size_t)i * K_DIM);

    float m = 0.0f;
    for (int c = t; c < K_DIM / 4; c += 256) {
        float4 v = row4[c];
        m = fmaxf(m, fmaxf(fmaxf(fabsf(v.x), fabsf(v.y)), fmaxf(fabsf(v.z), fabsf(v.w))));
    }
#pragma unroll
    for (int o = 16; o; o >>= 1) m = fmaxf(m, __shfl_xor_sync(~0u, m, o));
    __shared__ float red[8];
    __shared__ float mbc;
    if ((t & 31) == 0) red[t >> 5] = m;
    __syncthreads();
    if (t < 8) {
        float v = red[t];
#pragma unroll
        for (int o = 4; o; o >>= 1) v = fmaxf(v, __shfl_xor_sync(0xffu, v, o));
        if (t == 0) { mbc = v; g_m[i] = v; }
    }
    __syncthreads();
    const float mv = mbc;

    // pass 2: exp (row is L2-hot)
    __nv_bfloat16* erow = g_E + (size_t)i * K_PAD;
    for (int c = t; c < K_DIM / 4; c += 256) {
        float4 v = row4[c];
        __nv_bfloat16 o[4];
        o[0] = __float2bfloat16(__expf((fabsf(v.x) - mv) * LMB));
        o[1] = __float2bfloat16(__expf((fabsf(v.y) - mv) * LMB));
        o[2] = __float2bfloat16(__expf((fabsf(v.z) - mv) * LMB));
        o[3] = __float2bfloat16(__expf((fabsf(v.w) - mv) * LMB));
        *(uint2*)(erow + c * 4) = *(const uint2*)o;
    }
    // zero padding K_DIM..K_PAD (240 elems = 120 uint writes)
    if (t < 120) *(uint32_t*)(erow + K_DIM + 2 * t) = 0u;
}

// ---------------- kernel 2: wmma bf16 GEMM + log epilogue ----------------
__global__ void __launch_bounds__(256, 1)
lse_gemm_kernel(float* __restrict__ H)
{
    extern __shared__ char smem[];
    const uint32_t sb = smem_u32(smem);
    const int tid = (int)threadIdx.x;
    const int wid = tid >> 5;

    int rem = (int)blockIdx.x;
    int ti = 0;
    while (rem >= NTILES - ti) { rem -= NTILES - ti; ++ti; }
    const int tj = ti + rem;
    const int gi = ti * 128, gj = tj * 128;

    __shared__ float mjs[128];

    // warp tile: 4x2 warp grid, each warp 32(m) x 64(n)
    const int m0 = (wid & 3) * 32;
    const int n0 = (wid >> 2) * 64;

    wmma::fragment<wmma::accumulator, 16, 16, 16, float> acc[2][4];
#pragma unroll
    for (int a = 0; a < 2; ++a)
#pragma unroll
        for (int b = 0; b < 4; ++b) wmma::fill_fragment(acc[a][b], 0.0f);

    auto prefetch = [&](int s) {
        const int buf = s & (NBUF - 1);
        const uint32_t abase = sb + (uint32_t)buf * 2 * STAGE_BYTES;
        const uint32_t bbase = abase + STAGE_BYTES;
#pragma unroll
        for (int q = 0; q < 4; ++q) {
            int c = tid + 256 * q;            // 0..1023
            int isB = c >> 9;
            int cc = c & 511;
            int row = cc >> 2, sub = cc & 3;
            uint32_t dst = (isB ? bbase : abase) + (uint32_t)(row * (ESTR * 2) + sub * 16);
            const __nv_bfloat16* src =
                g_E + (size_t)((isB ? gj : gi) + row) * K_PAD + (size_t)s * KTS + sub * 8;
            cp16(dst, src);
        }
        cp_commit();
    };

    prefetch(0); prefetch(1); prefetch(2);

#pragma unroll 1
    for (int s = 0; s < NSTG; ++s) {
        if (s < NSTG - 2)       cp_wait<2>();
        else if (s == NSTG - 2) cp_wait<1>();
        else                    cp_wait<0>();
        __syncthreads();
        if (s + 3 < NSTG) prefetch(s + 3);

        const int buf = s & (NBUF - 1);
        const __nv_bfloat16* A = (const __nv_bfloat16*)(smem + buf * 2 * STAGE_BYTES);
        const __nv_bfloat16* B = (const __nv_bfloat16*)(smem + buf * 2 * STAGE_BYTES + STAGE_BYTES);
#pragma unroll
        for (int kk = 0; kk < KTS; kk += 16) {
            wmma::fragment<wmma::matrix_a, 16, 16, 16, __nv_bfloat16, wmma::row_major> af[2];
            wmma::fragment<wmma::matrix_b, 16, 16, 16, __nv_bfloat16, wmma::col_major> bfr[4];
#pragma unroll
            for (int a = 0; a < 2; ++a)
                wmma::load_matrix_sync(af[a], A + (m0 + a * 16) * ESTR + kk, ESTR);
#pragma unroll
            for (int b = 0; b < 4; ++b)
                wmma::load_matrix_sync(bfr[b], B + (n0 + b * 16) * ESTR + kk, ESTR);
#pragma unroll
            for (int a = 0; a < 2; ++a)
#pragma unroll
                for (int b = 0; b < 4; ++b)
                    wmma::mma_sync(acc[a][b], af[a], bfr[b], acc[a][b]);
        }
    }
    __syncthreads();   // all compute done before scratch reuse of pipeline smem

    // ---- epilogue: dump accumulators to smem scratch, apply m_i+m_j+log/L ----
    float* scratch = (float*)smem;
#pragma unroll
    for (int a = 0; a < 2; ++a)
#pragma unroll
        for (int b = 0; b < 4; ++b)
            wmma::store_matrix_sync(scratch + (size_t)(m0 + a * 16) * LDC + (n0 + b * 16),
                                    acc[a][b], LDC, wmma::mem_row_major);
    if (tid < 128) mjs[tid] = g_m[gj + tid];
    __syncthreads();

    const int r = tid >> 1, half = tid & 1;
    const float mi_v = g_m[gi + r];
    const float invL = 1.0f / LMB;
    const float* srow = scratch + (size_t)r * LDC + half * 64;
    const int cbase = half * 64;

#pragma unroll 1
    for (int c8 = 0; c8 < 64; c8 += 8) {
        float vals[8];
#pragma unroll
        for (int q = 0; q < 8; ++q)
            vals[q] = mi_v + mjs[cbase + c8 + q] + __logf(srow[c8 + q]) * invL;
        float4 v0 = make_float4(vals[0], vals[1], vals[2], vals[3]);
        float4 v1 = make_float4(vals[4], vals[5], vals[6], vals[7]);
        *(float4*)&H[(size_t)(gi + r) * N_DIM + gj + cbase + c8]     = v0;
        *(float4*)&H[(size_t)(gi + r) * N_DIM + gj + cbase + c8 + 4] = v1;
        if (ti != tj) {
#pragma unroll
            for (int q = 0; q < 8; ++q)
                H[(size_t)(gj + cbase + c8 + q) * N_DIM + gi + r] = vals[q];
        }
    }
}

// ---------------- launcher ----------------
extern "C" void kernel_launch(void* const* d_in, const int* in_sizes, int n_in,
                              void* d_out, int out_size) {
    const float* W = (const float*)d_in[0];
    float* H = (float*)d_out;

    cudaFuncSetAttribute(lse_gemm_kernel, cudaFuncAttributeMaxDynamicSharedMemorySize, SMEM_DYN);

    prep_kernel<<<N_DIM, 256>>>(W);
    lse_gemm_kernel<<<NPAIRS, 256, SMEM_DYN>>>(H);
}